// round 2
// baseline (speedup 1.0000x reference)
#include <cuda_runtime.h>

#define NC 16
#define EPSV 1e-6f
#define B_DIM 2
#define D_DIM 8
#define H_DIM 96
#define W_DIM 96
#define DHW (D_DIM*H_DIM*W_DIM)     // 73728
#define HW  (H_DIM*W_DIM)           // 9216

#define TH 8
#define TW 32
#define NTHREADS (TH*TW)            // 256
#define HALO_H (TH+2)               // 10
#define HALO_W (TW+2)               // 34
#define NLOC   (3*HALO_H*HALO_W)    // 1020 halo locations (kt,yy,xx)
#define CSTRIDE 20                  // 16 channels + 4 pad floats (20 mod 8 == 4 -> conflict-free LDS.128)
#define SH_ELEMS (NLOC*CSTRIDE)     // 20400 floats
#define SV_ELEMS (27*NTHREADS)      // 6912 floats
#define TAILW_OFF (SH_ELEMS + SV_ELEMS)
#define SMEM_FLOATS (TAILW_OFF + 256)
#define SMEM_BYTES (SMEM_FLOATS * 4)   // 110,272 B -> 2 CTAs/SM

// 9.4 MB scratch for head output, channel-contiguous: h[b][d][y][x][c]
__device__ float g_h[(size_t)B_DIM * DHW * NC];

// ---------------------------------------------------------------------------
// Kernel 1: h = relu(head_w @ x). Writes c-contiguous (4x STG.128 / location).
// ---------------------------------------------------------------------------
__global__ void head_kernel(const float* __restrict__ x,
                            const float* __restrict__ head_w) {
    __shared__ float sw[NC * NC];
    if (threadIdx.x < NC * NC) sw[threadIdx.x] = head_w[threadIdx.x];
    __syncthreads();

    int idx = blockIdx.x * blockDim.x + threadIdx.x;   // over b*D*H*W
    if (idx >= B_DIM * DHW) return;
    int b = idx / DHW;
    int s = idx - b * DHW;

    const float* xb = x + (size_t)b * NC * DHW + s;
    float xv[NC];
#pragma unroll
    for (int c = 0; c < NC; c++) xv[c] = xb[(size_t)c * DHW];

    float hv[NC];
#pragma unroll
    for (int o = 0; o < NC; o++) {
        float a = 0.f;
#pragma unroll
        for (int c = 0; c < NC; c++) a = fmaf(sw[o * NC + c], xv[c], a);
        hv[o] = fmaxf(a, 0.f);
    }
    float4* hb = (float4*)(g_h + (size_t)idx * NC);
#pragma unroll
    for (int q = 0; q < 4; q++)
        hb[q] = make_float4(hv[4*q], hv[4*q+1], hv[4*q+2], hv[4*q+3]);
}

// ---------------------------------------------------------------------------
// Kernel 2: per-location rank-degenerate NMF + tail, vectorized X access.
// ---------------------------------------------------------------------------
__global__ void __launch_bounds__(NTHREADS, 2)
nmf_kernel(const float* __restrict__ tail_w, float* __restrict__ out) {
    extern __shared__ float smem[];
    float* sh = smem;                 // [kt][yy][xx][CSTRIDE] halo tile
    float* sv = smem + SH_ELEMS;      // [27][256] per-thread v
    float* st = smem + TAILW_OFF;     // [256] tail weights

    const int tid = threadIdx.x;
    const int bz = blockIdx.z;
    const int b  = bz >> 3;
    const int d  = bz & 7;
    const int y0 = blockIdx.y * TH;
    const int x0 = blockIdx.x * TW;

    if (tid < NC * NC) st[tid] = tail_w[tid];

    // ---- stage halo tile: coalesced 64B/thread copies ----
    {
        const size_t hbase = (size_t)b * DHW * NC;
        for (int i = tid; i < NLOC; i += NTHREADS) {
            int xx = i % HALO_W;
            int r  = i / HALO_W;
            int yy = r % HALO_H;
            int kt = r / HALO_H;
            int gd = min(max(d + kt - 1, 0), D_DIM - 1);
            int gy = min(max(y0 + yy - 1, 0), H_DIM - 1);
            int gx = min(max(x0 + xx - 1, 0), W_DIM - 1);
            const float4* src = (const float4*)(g_h + hbase
                               + (size_t)((gd * H_DIM + gy) * W_DIM + gx) * NC);
            float4* dst = (float4*)(sh + i * CSTRIDE);
            dst[0] = src[0]; dst[1] = src[1]; dst[2] = src[2]; dst[3] = src[3];
        }
    }
    __syncthreads();

    const int ty = tid >> 5;
    const int tx = tid & 31;
    // X(c, k=(ki*3+kj)*3+kt) at:
    //   sh + ((kt*HALO_H + ty+ki)*HALO_W + tx+kj)*CSTRIDE + c
    const float* shp = sh + (ty * HALO_W + tx) * CSTRIDE;

#define COL_OFF(ki,kj,kt) (((kt)*HALO_H + (ki)) * HALO_W + (kj)) * CSTRIDE

    float u[NC];
#pragma unroll
    for (int c = 0; c < NC; c++) u[c] = 0.f;

    // ---- init pass: u[c] = mean_k X, v[k] = mean_c X ----
#pragma unroll
    for (int kk = 0; kk < 9; kk++) {          // kk = ki*3+kj
        const int ki = kk / 3, kj = kk % 3;
#pragma unroll
        for (int kt = 0; kt < 3; kt++) {
            const float4* p = (const float4*)(shp + COL_OFF(ki, kj, kt));
            float s = 0.f;
#pragma unroll
            for (int q = 0; q < 4; q++) {
                float4 xv = p[q];
                s += xv.x + xv.y + xv.z + xv.w;
                u[4*q+0] += xv.x; u[4*q+1] += xv.y;
                u[4*q+2] += xv.z; u[4*q+3] += xv.w;
            }
            sv[(kk * 3 + kt) * NTHREADS + tid] = s * (1.f / 16.f);
        }
    }
#pragma unroll
    for (int c = 0; c < NC; c++) u[c] *= (1.f / 27.f);

    // ---- 3 NMF steps ----
#pragma unroll 1
    for (int step = 0; step < 3; step++) {
        float uu = 0.f;
#pragma unroll
        for (int c = 0; c < NC; c++) uu = fmaf(u[c], u[c], uu);
        const float t_uu = 3.f * uu;

        float nu[NC];
#pragma unroll
        for (int c = 0; c < NC; c++) nu[c] = 0.f;
        float vv = 0.f;

#pragma unroll
        for (int kk = 0; kk < 9; kk++) {
            const int ki = kk / 3, kj = kk % 3;
#pragma unroll
            for (int kt = 0; kt < 3; kt++) {
                const float4* p = (const float4*)(shp + COL_OFF(ki, kj, kt));
                float4 xq[4];
#pragma unroll
                for (int q = 0; q < 4; q++) xq[q] = p[q];

                float num = 0.f;
#pragma unroll
                for (int q = 0; q < 4; q++) {
                    num = fmaf(u[4*q+0], xq[q].x, num);
                    num = fmaf(u[4*q+1], xq[q].y, num);
                    num = fmaf(u[4*q+2], xq[q].z, num);
                    num = fmaf(u[4*q+3], xq[q].w, num);
                }

                const int svi = (kk * 3 + kt) * NTHREADS + tid;
                float vk = sv[svi];
                float vn = vk * num * __frcp_rn(fmaf(t_uu, vk, EPSV));
                sv[svi] = vn;
                vv = fmaf(vn, vn, vv);
#pragma unroll
                for (int q = 0; q < 4; q++) {
                    nu[4*q+0] = fmaf(xq[q].x, vn, nu[4*q+0]);
                    nu[4*q+1] = fmaf(xq[q].y, vn, nu[4*q+1]);
                    nu[4*q+2] = fmaf(xq[q].z, vn, nu[4*q+2]);
                    nu[4*q+3] = fmaf(xq[q].w, vn, nu[4*q+3]);
                }
            }
        }
        const float t_vv = 3.f * vv;
#pragma unroll
        for (int c = 0; c < NC; c++)
            u[c] = u[c] * nu[c] * __frcp_rn(fmaf(t_vv, u[c], EPSV));
    }

    // ---- center tap + tail GEMV + relu ----
    const float v13 = sv[13 * NTHREADS + tid];
    float uvc[NC];
#pragma unroll
    for (int c = 0; c < NC; c++) uvc[c] = 3.f * u[c] * v13;

    const size_t outbase = (size_t)b * NC * DHW + (size_t)d * HW
                         + (size_t)(y0 + ty) * W_DIM + (x0 + tx);
#pragma unroll
    for (int i = 0; i < NC; i++) {
        float a = 0.f;
#pragma unroll
        for (int o = 0; o < NC; o++) a = fmaf(st[i * NC + o], uvc[o], a);
        out[outbase + (size_t)i * DHW] = fmaxf(a, 0.f);
    }
}

// ---------------------------------------------------------------------------
extern "C" void kernel_launch(void* const* d_in, const int* in_sizes, int n_in,
                              void* d_out, int out_size) {
    const float* x      = (const float*)d_in[0];
    const float* head_w = (const float*)d_in[1];
    const float* tail_w = (const float*)d_in[2];
    float* out = (float*)d_out;

    (void)in_sizes; (void)n_in; (void)out_size;

    cudaFuncSetAttribute(nmf_kernel,
                         cudaFuncAttributeMaxDynamicSharedMemorySize,
                         SMEM_BYTES);

    {   // head: one thread per spatial location
        int total = B_DIM * DHW;
        int threads = 256;
        int blocks = (total + threads - 1) / threads;
        head_kernel<<<blocks, threads>>>(x, head_w);
    }
    {
        dim3 grid(W_DIM / TW, H_DIM / TH, B_DIM * D_DIM);   // (3, 12, 16)
        nmf_kernel<<<grid, NTHREADS, SMEM_BYTES>>>(tail_w, out);
    }
}

// round 3
// speedup vs baseline: 2.5590x; 2.5590x over previous
#include <cuda_runtime.h>

#define NC 16
#define EPSV 1e-6f
#define B_DIM 2
#define D_DIM 8
#define H_DIM 96
#define W_DIM 96
#define DHW (D_DIM*H_DIM*W_DIM)     // 73728
#define HW  (H_DIM*W_DIM)           // 9216

#define TH 8
#define TW 32
#define NTHREADS (TH*TW)            // 256
#define HALO_H (TH+2)               // 10
#define HALO_W (TW+2)               // 34
#define NLOC   (3*HALO_H*HALO_W)    // 1020 halo locations (kt,yy,xx)
#define CSTRIDE 20                  // 16 ch + 4 pad (20 mod 8 == 4 -> conflict-free LDS.128)
#define SH_ELEMS (NLOC*CSTRIDE)     // 20400 floats
#define SV_ELEMS (27*NTHREADS)      // 6912 floats
#define TAILW_OFF (SH_ELEMS + SV_ELEMS)
#define SMEM_FLOATS (TAILW_OFF + 256)
#define SMEM_BYTES (SMEM_FLOATS * 4)   // 110,272 B -> 2 CTAs/SM

// 9.4 MB scratch for head output, channel-contiguous: h[b][d][y][x][c]
__device__ float g_h[(size_t)B_DIM * DHW * NC];

// ---------------------------------------------------------------------------
// Kernel 1: h = relu(head_w @ x). Writes c-contiguous (4x STG.128 / location).
// ---------------------------------------------------------------------------
__global__ void head_kernel(const float* __restrict__ x,
                            const float* __restrict__ head_w) {
    __shared__ float sw[NC * NC];
    if (threadIdx.x < NC * NC) sw[threadIdx.x] = head_w[threadIdx.x];
    __syncthreads();

    int idx = blockIdx.x * blockDim.x + threadIdx.x;   // over b*D*H*W
    if (idx >= B_DIM * DHW) return;
    int b = idx / DHW;
    int s = idx - b * DHW;

    const float* xb = x + (size_t)b * NC * DHW + s;
    float xv[NC];
#pragma unroll
    for (int c = 0; c < NC; c++) xv[c] = xb[(size_t)c * DHW];

    float hv[NC];
#pragma unroll
    for (int o = 0; o < NC; o++) {
        float a = 0.f;
#pragma unroll
        for (int c = 0; c < NC; c++) a = fmaf(sw[o * NC + c], xv[c], a);
        hv[o] = fmaxf(a, 0.f);
    }
    float4* hb = (float4*)(g_h + (size_t)idx * NC);
#pragma unroll
    for (int q = 0; q < 4; q++)
        hb[q] = make_float4(hv[4*q], hv[4*q+1], hv[4*q+2], hv[4*q+3]);
}

// ---------------------------------------------------------------------------
// Kernel 2: per-location rank-degenerate NMF + tail.
// Rolled kk loop (9 iters), vectorized LDS.128 column access.
// ---------------------------------------------------------------------------
__global__ void __launch_bounds__(NTHREADS)
nmf_kernel(const float* __restrict__ tail_w, float* __restrict__ out) {
    extern __shared__ float smem[];
    float* sh = smem;                 // [kt][yy][xx][CSTRIDE] halo tile
    float* sv = smem + SH_ELEMS;      // [27][256] per-thread v
    float* st = smem + TAILW_OFF;     // [256] tail weights

    const int tid = threadIdx.x;
    const int bz = blockIdx.z;
    const int b  = bz >> 3;
    const int d  = bz & 7;
    const int y0 = blockIdx.y * TH;
    const int x0 = blockIdx.x * TW;

    if (tid < NC * NC) st[tid] = tail_w[tid];

    // ---- stage halo tile: coalesced 64B/thread copies ----
    {
        const size_t hbase = (size_t)b * DHW * NC;
        for (int i = tid; i < NLOC; i += NTHREADS) {
            int xx = i % HALO_W;
            int r  = i / HALO_W;
            int yy = r % HALO_H;
            int kt = r / HALO_H;
            int gd = min(max(d + kt - 1, 0), D_DIM - 1);
            int gy = min(max(y0 + yy - 1, 0), H_DIM - 1);
            int gx = min(max(x0 + xx - 1, 0), W_DIM - 1);
            const float4* src = (const float4*)(g_h + hbase
                               + (size_t)((gd * H_DIM + gy) * W_DIM + gx) * NC);
            float4* dst = (float4*)(sh + i * CSTRIDE);
            dst[0] = src[0]; dst[1] = src[1]; dst[2] = src[2]; dst[3] = src[3];
        }
    }
    __syncthreads();

    const int ty = tid >> 5;
    const int tx = tid & 31;
    // Column (ki,kj,kt): sh + ((kt*HALO_H + ty+ki)*HALO_W + tx+kj)*CSTRIDE
    const float* shp = sh + (ty * HALO_W + tx) * CSTRIDE;

    float u[NC];
#pragma unroll
    for (int c = 0; c < NC; c++) u[c] = 0.f;

    // ---- init pass: u[c] = mean_k X, v[k] = mean_c X ----
#pragma unroll 1
    for (int kk = 0; kk < 9; kk++) {          // kk = ki*3+kj
        const int ki = kk / 3, kj = kk - 3 * ki;
        const float* pbase = shp + (ki * HALO_W + kj) * CSTRIDE;
#pragma unroll
        for (int kt = 0; kt < 3; kt++) {
            const float4* p = (const float4*)(pbase + kt * (HALO_H * HALO_W * CSTRIDE));
            float s = 0.f;
#pragma unroll
            for (int q = 0; q < 4; q++) {
                float4 xv = p[q];
                s += (xv.x + xv.y) + (xv.z + xv.w);
                u[4*q+0] += xv.x; u[4*q+1] += xv.y;
                u[4*q+2] += xv.z; u[4*q+3] += xv.w;
            }
            sv[(kk * 3 + kt) * NTHREADS + tid] = s * (1.f / 16.f);
        }
    }
#pragma unroll
    for (int c = 0; c < NC; c++) u[c] *= (1.f / 27.f);

    // ---- 3 NMF steps ----
#pragma unroll 1
    for (int step = 0; step < 3; step++) {
        float uu = 0.f;
#pragma unroll
        for (int c = 0; c < NC; c++) uu = fmaf(u[c], u[c], uu);
        const float t_uu = 3.f * uu;

        float nu[NC];
#pragma unroll
        for (int c = 0; c < NC; c++) nu[c] = 0.f;
        float vv = 0.f;

#pragma unroll 1
        for (int kk = 0; kk < 9; kk++) {
            const int ki = kk / 3, kj = kk - 3 * ki;
            const float* pbase = shp + (ki * HALO_W + kj) * CSTRIDE;
#pragma unroll
            for (int kt = 0; kt < 3; kt++) {
                const float4* p = (const float4*)(pbase + kt * (HALO_H * HALO_W * CSTRIDE));

                float num = 0.f;
                float4 x0q = p[0], x1q = p[1], x2q = p[2], x3q = p[3];
                num = fmaf(u[0],  x0q.x, num); num = fmaf(u[1],  x0q.y, num);
                num = fmaf(u[2],  x0q.z, num); num = fmaf(u[3],  x0q.w, num);
                num = fmaf(u[4],  x1q.x, num); num = fmaf(u[5],  x1q.y, num);
                num = fmaf(u[6],  x1q.z, num); num = fmaf(u[7],  x1q.w, num);
                num = fmaf(u[8],  x2q.x, num); num = fmaf(u[9],  x2q.y, num);
                num = fmaf(u[10], x2q.z, num); num = fmaf(u[11], x2q.w, num);
                num = fmaf(u[12], x3q.x, num); num = fmaf(u[13], x3q.y, num);
                num = fmaf(u[14], x3q.z, num); num = fmaf(u[15], x3q.w, num);

                const int svi = (kk * 3 + kt) * NTHREADS + tid;
                float vk = sv[svi];
                float vn = vk * num * __frcp_rn(fmaf(t_uu, vk, EPSV));
                sv[svi] = vn;
                vv = fmaf(vn, vn, vv);

                nu[0]  = fmaf(x0q.x, vn, nu[0]);  nu[1]  = fmaf(x0q.y, vn, nu[1]);
                nu[2]  = fmaf(x0q.z, vn, nu[2]);  nu[3]  = fmaf(x0q.w, vn, nu[3]);
                nu[4]  = fmaf(x1q.x, vn, nu[4]);  nu[5]  = fmaf(x1q.y, vn, nu[5]);
                nu[6]  = fmaf(x1q.z, vn, nu[6]);  nu[7]  = fmaf(x1q.w, vn, nu[7]);
                nu[8]  = fmaf(x2q.x, vn, nu[8]);  nu[9]  = fmaf(x2q.y, vn, nu[9]);
                nu[10] = fmaf(x2q.z, vn, nu[10]); nu[11] = fmaf(x2q.w, vn, nu[11]);
                nu[12] = fmaf(x3q.x, vn, nu[12]); nu[13] = fmaf(x3q.y, vn, nu[13]);
                nu[14] = fmaf(x3q.z, vn, nu[14]); nu[15] = fmaf(x3q.w, vn, nu[15]);
            }
        }
        const float t_vv = 3.f * vv;
#pragma unroll
        for (int c = 0; c < NC; c++)
            u[c] = u[c] * nu[c] * __frcp_rn(fmaf(t_vv, u[c], EPSV));
    }

    // ---- center tap + tail GEMV + relu ----
    const float v13 = sv[13 * NTHREADS + tid];
    float uvc[NC];
#pragma unroll
    for (int c = 0; c < NC; c++) uvc[c] = 3.f * u[c] * v13;

    const size_t outbase = (size_t)b * NC * DHW + (size_t)d * HW
                         + (size_t)(y0 + ty) * W_DIM + (x0 + tx);
#pragma unroll
    for (int i = 0; i < NC; i++) {
        float a = 0.f;
#pragma unroll
        for (int o = 0; o < NC; o++) a = fmaf(st[i * NC + o], uvc[o], a);
        out[outbase + (size_t)i * DHW] = fmaxf(a, 0.f);
    }
}

// ---------------------------------------------------------------------------
extern "C" void kernel_launch(void* const* d_in, const int* in_sizes, int n_in,
                              void* d_out, int out_size) {
    const float* x      = (const float*)d_in[0];
    const float* head_w = (const float*)d_in[1];
    const float* tail_w = (const float*)d_in[2];
    float* out = (float*)d_out;

    (void)in_sizes; (void)n_in; (void)out_size;

    cudaFuncSetAttribute(nmf_kernel,
                         cudaFuncAttributeMaxDynamicSharedMemorySize,
                         SMEM_BYTES);

    {   // head: one thread per spatial location
        int total = B_DIM * DHW;
        int threads = 256;
        int blocks = (total + threads - 1) / threads;
        head_kernel<<<blocks, threads>>>(x, head_w);
    }
    {
        dim3 grid(W_DIM / TW, H_DIM / TH, B_DIM * D_DIM);   // (3, 12, 16)
        nmf_kernel<<<grid, NTHREADS, SMEM_BYTES>>>(tail_w, out);
    }
}